// round 11
// baseline (speedup 1.0000x reference)
#include <cuda_runtime.h>
#include <cuda_bf16.h>
#include <cstdint>
#include <cstddef>

#define BB 8
#define NN 2048
#define DDIM 512

typedef __nv_bfloat16 bf16;

// ---------------------------------------------------------------------------
// Scratch (static device globals: allocation-free rule)
// ---------------------------------------------------------------------------
__device__ bf16 g_xh[(size_t)BB * NN * DDIM];
__device__ bf16 g_xl[(size_t)BB * NN * DDIM];
__device__ bf16 g_wqh[(size_t)DDIM * DDIM];
__device__ bf16 g_wql[(size_t)DDIM * DDIM];
__device__ bf16 g_wkh[(size_t)DDIM * DDIM];
__device__ bf16 g_wkl[(size_t)DDIM * DDIM];
__device__ bf16 g_wvh[(size_t)DDIM * DDIM];
__device__ bf16 g_wvl[(size_t)DDIM * DDIM];
__device__ bf16 g_Qh[(size_t)BB * NN * DDIM];
__device__ bf16 g_Ql[(size_t)BB * NN * DDIM];
__device__ bf16 g_Kh[(size_t)BB * NN * DDIM];
__device__ bf16 g_Kl[(size_t)BB * NN * DDIM];
__device__ bf16 g_Vh[(size_t)BB * NN * DDIM];
__device__ bf16 g_Vl[(size_t)BB * NN * DDIM];
__device__ bf16 g_Wmh[(size_t)BB * NN * NN];
__device__ bf16 g_Wml[(size_t)BB * NN * NN];
__device__ float g_rs[(size_t)BB * NN];

// ---------------------------------------------------------------------------
// Low-level helpers (family-baseline PTX only: cp.async / ldmatrix / mma.sync)
// ---------------------------------------------------------------------------
__device__ __forceinline__ uint32_t smem_to_u32(const void* p) {
    uint32_t a;
    asm("{ .reg .u64 t; cvta.to.shared.u64 t, %1; cvt.u32.u64 %0, t; }"
        : "=r"(a) : "l"(p));
    return a;
}
__device__ __forceinline__ void cp16(uint32_t dst, const void* src) {
    asm volatile("cp.async.cg.shared.global [%0], [%1], 16;" :: "r"(dst), "l"(src));
}
__device__ __forceinline__ void cp_commit() {
    asm volatile("cp.async.commit_group;" ::: "memory");
}
__device__ __forceinline__ void cp_wait1() {
    asm volatile("cp.async.wait_group 1;" ::: "memory");
}
__device__ __forceinline__ void cp_wait0() {
    asm volatile("cp.async.wait_group 0;" ::: "memory");
}
__device__ __forceinline__ void ldsm4(uint32_t* r, uint32_t addr) {
    asm volatile("ldmatrix.sync.aligned.m8n8.x4.shared.b16 {%0,%1,%2,%3}, [%4];"
                 : "=r"(r[0]), "=r"(r[1]), "=r"(r[2]), "=r"(r[3]) : "r"(addr));
}
__device__ __forceinline__ void ldsm4t(uint32_t* r, uint32_t addr) {
    asm volatile("ldmatrix.sync.aligned.m8n8.x4.trans.shared.b16 {%0,%1,%2,%3}, [%4];"
                 : "=r"(r[0]), "=r"(r[1]), "=r"(r[2]), "=r"(r[3]) : "r"(addr));
}
__device__ __forceinline__ void mma16816(float* c, const uint32_t* a, const uint32_t* b) {
    asm volatile(
        "mma.sync.aligned.m16n8k16.row.col.f32.bf16.bf16.f32 "
        "{%0,%1,%2,%3}, {%4,%5,%6,%7}, {%8,%9}, {%0,%1,%2,%3};"
        : "+f"(c[0]), "+f"(c[1]), "+f"(c[2]), "+f"(c[3])
        : "r"(a[0]), "r"(a[1]), "r"(a[2]), "r"(a[3]), "r"(b[0]), "r"(b[1]));
}
__device__ __forceinline__ uint32_t pack_bf16(bf16 a, bf16 b) {
    return (uint32_t)__bfloat16_as_ushort(a) | ((uint32_t)__bfloat16_as_ushort(b) << 16);
}
__device__ __forceinline__ void split_val(float v, bf16& h, bf16& l) {
    h = __float2bfloat16(v);
    l = __float2bfloat16(v - __bfloat162float(h));
}

// ---------------------------------------------------------------------------
// SMEM: 3 stages x (Ah 16K | Al 16K | Bh 16K | Bl 16K) = 192 KB
// ---------------------------------------------------------------------------
static constexpr int SLAB = 16384;
static constexpr int STAGE = 4 * SLAB;        // 65536
static constexpr int SMEM_TOTAL = 3 * STAGE;  // 196608

// k-major loader: 128 rows x 64 k. 256 threads, 4 cp16 each.
__device__ __forceinline__ void load_km(const bf16* src, size_t ld, uint32_t sbase, int t)
{
    const int col = t & 7, r0 = t >> 3;
    #pragma unroll
    for (int p = 0; p < 4; p++) {
        const int row = r0 + 32 * p;
        const uint32_t off = row * 128 + ((col ^ (row & 7)) << 4);
        cp16(sbase + off, src + (size_t)row * ld + col * 8);
    }
}
// n-major V loader: 64 k-rows x 128 n-cols. 256 threads, 4 cp16 each.
__device__ __forceinline__ void load_bn(const bf16* src, size_t ld, uint32_t sbase, int t)
{
    const int col = t & 15, r0 = t >> 4;
    #pragma unroll
    for (int p = 0; p < 4; p++) {
        const int row = r0 + 16 * p;
        const uint32_t off = row * 256 + ((col ^ (row & 7)) << 4);
        cp16(sbase + off, src + (size_t)row * ld + col * 8);
    }
}

// ---------------------------------------------------------------------------
// Fragment loaders (one kk step = 16 k-values)
// ---------------------------------------------------------------------------
__device__ __forceinline__ void lda_frag(uint32_t sAh, uint32_t sAl, int kk, int lane,
                                         int wm0, uint32_t aH[4][4], uint32_t aL[4][4])
{
    const int ar = lane & 15;
    const int ac = 2 * kk + (lane >> 4);
    #pragma unroll
    for (int i = 0; i < 4; i++) {
        const int row = wm0 + i * 16 + ar;
        const uint32_t off = row * 128 + ((ac ^ (row & 7)) << 4);
        ldsm4(aH[i], sAh + off);
        ldsm4(aL[i], sAl + off);
    }
}
__device__ __forceinline__ void ldb_frag_nt(uint32_t sBh, uint32_t sBl, int kk, int lane,
                                            int wn0, uint32_t bH[4][2], uint32_t bL[4][2])
{
    const int br = (lane & 7) + ((lane >> 4) & 1) * 8;
    const int bc = 2 * kk + ((lane >> 3) & 1);
    #pragma unroll
    for (int jj = 0; jj < 2; jj++) {
        const int row = wn0 + jj * 16 + br;
        const uint32_t off = row * 128 + ((bc ^ (row & 7)) << 4);
        uint32_t tH[4], tL[4];
        ldsm4(tH, sBh + off);
        ldsm4(tL, sBl + off);
        bH[2 * jj][0] = tH[0]; bH[2 * jj][1] = tH[1];
        bH[2 * jj + 1][0] = tH[2]; bH[2 * jj + 1][1] = tH[3];
        bL[2 * jj][0] = tL[0]; bL[2 * jj][1] = tL[1];
        bL[2 * jj + 1][0] = tL[2]; bL[2 * jj + 1][1] = tL[3];
    }
}
__device__ __forceinline__ void ldb_frag_tr(uint32_t sVh, uint32_t sVl, int kk, int lane,
                                            int wn0, uint32_t bH[4][2], uint32_t bL[4][2])
{
    const int br = kk * 16 + (lane & 7) + ((lane >> 3) & 1) * 8;
    #pragma unroll
    for (int jj = 0; jj < 2; jj++) {
        const int ch = (wn0 >> 3) + 2 * jj + (lane >> 4);
        const uint32_t off = br * 256 + ((ch ^ (br & 7)) << 4);
        uint32_t tH[4], tL[4];
        ldsm4t(tH, sVh + off);
        ldsm4t(tL, sVl + off);
        bH[2 * jj][0] = tH[0]; bH[2 * jj][1] = tH[1];
        bH[2 * jj + 1][0] = tH[2]; bH[2 * jj + 1][1] = tH[3];
        bL[2 * jj][0] = tL[0]; bL[2 * jj][1] = tL[1];
        bL[2 * jj + 1][0] = tL[2]; bL[2 * jj + 1][1] = tL[3];
    }
}

// 48 MMAs of one kk step, pass-major (16-deep accumulator reuse distance).
__device__ __forceinline__ void mma_block(float c[4][4][4],
                                          uint32_t aH[4][4], uint32_t aL[4][4],
                                          uint32_t bH[4][2], uint32_t bL[4][2])
{
    #pragma unroll
    for (int j = 0; j < 4; j++)
        #pragma unroll
        for (int i = 0; i < 4; i++)
            mma16816(c[i][j], aH[i], bH[j]);
    #pragma unroll
    for (int j = 0; j < 4; j++)
        #pragma unroll
        for (int i = 0; i < 4; i++)
            mma16816(c[i][j], aH[i], bL[j]);
    #pragma unroll
    for (int j = 0; j < 4; j++)
        #pragma unroll
        for (int i = 0; i < 4; i++)
            mma16816(c[i][j], aL[i], bH[j]);
}

__device__ __forceinline__ void compute_nt(uint32_t base, float c[4][4][4],
                                           int lane, int wm0, int wn0)
{
    const uint32_t sAh = base, sAl = base + SLAB;
    const uint32_t sBh = base + 2 * SLAB, sBl = base + 3 * SLAB;
    uint32_t aH[2][4][4], aL[2][4][4], bH[2][4][2], bL[2][4][2];
    lda_frag(sAh, sAl, 0, lane, wm0, aH[0], aL[0]);
    ldb_frag_nt(sBh, sBl, 0, lane, wn0, bH[0], bL[0]);
    #pragma unroll
    for (int kk = 0; kk < 4; kk++) {
        const int cur = kk & 1;
        if (kk < 3) {
            lda_frag(sAh, sAl, kk + 1, lane, wm0, aH[cur ^ 1], aL[cur ^ 1]);
            ldb_frag_nt(sBh, sBl, kk + 1, lane, wn0, bH[cur ^ 1], bL[cur ^ 1]);
        }
        mma_block(c, aH[cur], aL[cur], bH[cur], bL[cur]);
    }
}

__device__ __forceinline__ void compute_tr(uint32_t base, float c[4][4][4],
                                           int lane, int wm0, int wn0)
{
    const uint32_t sAh = base, sAl = base + SLAB;
    const uint32_t sVh = base + 2 * SLAB, sVl = base + 3 * SLAB;
    uint32_t aH[2][4][4], aL[2][4][4], bH[2][4][2], bL[2][4][2];
    lda_frag(sAh, sAl, 0, lane, wm0, aH[0], aL[0]);
    ldb_frag_tr(sVh, sVl, 0, lane, wn0, bH[0], bL[0]);
    #pragma unroll
    for (int kk = 0; kk < 4; kk++) {
        const int cur = kk & 1;
        if (kk < 3) {
            lda_frag(sAh, sAl, kk + 1, lane, wm0, aH[cur ^ 1], aL[cur ^ 1]);
            ldb_frag_tr(sVh, sVl, kk + 1, lane, wn0, bH[cur ^ 1], bL[cur ^ 1]);
        }
        mma_block(c, aH[cur], aL[cur], bH[cur], bL[cur]);
    }
}

#define ZERO_ACC(c)                                  \
    _Pragma("unroll")                                \
    for (int i = 0; i < 4; i++)                      \
        _Pragma("unroll")                            \
        for (int j = 0; j < 4; j++)                  \
            _Pragma("unroll")                        \
            for (int k = 0; k < 4; k++) c[i][j][k] = 0.f;

// ---------------------------------------------------------------------------
// Per-kernel chunk issuers: decode (tile, k-chunk) from the global chunk id
// and issue the 4 slab loads into the given stage base.  One commit per call
// site keeps cp.async group accounting uniform.
// ---------------------------------------------------------------------------
// qkv tiles: 1536 = x(4: n0) * y(128: m0) * z(3: matrix).  NIT = 8.
__device__ __forceinline__ void qkv_issue(int gc, int bid, int grid, int tid, uint32_t dst)
{
    const int t = bid + (gc >> 3) * grid;
    const int k0 = (gc & 7) << 6;
    const int n0 = (t & 3) << 7;
    const int m0 = ((t >> 2) & 127) << 7;
    const int z = t >> 9;
    const bf16* Wh_ = (z == 0) ? g_wqh : (z == 1) ? g_wkh : g_wvh;
    const bf16* Wl_ = (z == 0) ? g_wql : (z == 1) ? g_wkl : g_wvl;
    load_km(g_xh + (size_t)m0 * DDIM + k0, DDIM, dst, tid);
    load_km(g_xl + (size_t)m0 * DDIM + k0, DDIM, dst + SLAB, tid);
    load_km(Wh_ + (size_t)n0 * DDIM + k0, DDIM, dst + 2 * SLAB, tid);
    load_km(Wl_ + (size_t)n0 * DDIM + k0, DDIM, dst + 3 * SLAB, tid);
}
// score tiles: 2048 = x(16: c0) * y(16: q0) * z(8: b).  NIT = 8.
__device__ __forceinline__ void score_issue(int gc, int bid, int grid, int tid, uint32_t dst)
{
    const int t = bid + (gc >> 3) * grid;
    const int k0 = (gc & 7) << 6;
    const int c0 = (t & 15) << 7;
    const int q0 = ((t >> 4) & 15) << 7;
    const int b = t >> 8;
    load_km(g_Qh + ((size_t)b * NN + q0) * DDIM + k0, DDIM, dst, tid);
    load_km(g_Ql + ((size_t)b * NN + q0) * DDIM + k0, DDIM, dst + SLAB, tid);
    load_km(g_Kh + ((size_t)b * NN + c0) * DDIM + k0, DDIM, dst + 2 * SLAB, tid);
    load_km(g_Kl + ((size_t)b * NN + c0) * DDIM + k0, DDIM, dst + 3 * SLAB, tid);
}
// out tiles: 512 = x(4: n0) * y(16: q0) * z(8: b).  NIT = 32.
__device__ __forceinline__ void out_issue(int gc, int bid, int grid, int tid, uint32_t dst)
{
    const int t = bid + (gc >> 5) * grid;
    const int k0 = (gc & 31) << 6;
    const int n0 = (t & 3) << 7;
    const int q0 = ((t >> 2) & 15) << 7;
    const int b = t >> 6;
    load_km(g_Wmh + ((size_t)b * NN + q0) * NN + k0, NN, dst, tid);
    load_km(g_Wml + ((size_t)b * NN + q0) * NN + k0, NN, dst + SLAB, tid);
    load_bn(g_Vh + ((size_t)b * NN + k0) * DDIM + n0, DDIM, dst + 2 * SLAB, tid);
    load_bn(g_Vl + ((size_t)b * NN + k0) * DDIM + n0, DDIM, dst + 3 * SLAB, tid);
}

// ---------------------------------------------------------------------------
// Kernel 1: QKV projections — persistent CTAs, continuous 3-stage ring.
// ---------------------------------------------------------------------------
__global__ __launch_bounds__(256, 1)
void qkv_mma_kernel(const float* __restrict__ bq, const float* __restrict__ bk,
                    const float* __restrict__ bv)
{
    extern __shared__ char smem[];
    const uint32_t sb = smem_to_u32(smem);
    const int tid = threadIdx.x, wid = tid >> 5, lane = tid & 31;
    const int wm0 = (wid & 1) * 64, wn0 = (wid >> 1) * 32;
    const int bid = blockIdx.x, grid = gridDim.x;
    const int NT = 1536;
    const int total = ((NT - 1 - bid) / grid + 1) * 8;

    qkv_issue(0, bid, grid, tid, sb);
    cp_commit();
    if (total > 1) qkv_issue(1, bid, grid, tid, sb + STAGE);
    cp_commit();

    float c[4][4][4];
    ZERO_ACC(c);
    int st = 0;
    for (int gc = 0; gc < total; gc++) {
        if (gc == total - 1) cp_wait0(); else cp_wait1();
        __syncthreads();
        compute_nt(sb + st * STAGE, c, lane, wm0, wn0);
        if (gc + 2 < total) {
            int st2 = st - 1; if (st2 < 0) st2 = 2;
            qkv_issue(gc + 2, bid, grid, tid, sb + st2 * STAGE);
        }
        cp_commit();
        if ((gc & 7) == 7) {
            const int t = bid + (gc >> 3) * grid;
            const int n0 = (t & 3) << 7;
            const int m0 = ((t >> 2) & 127) << 7;
            const int z = t >> 9;
            const float* bias = (z == 0) ? bq : (z == 1) ? bk : bv;
            bf16* Dh = (z == 0) ? g_Qh : (z == 1) ? g_Kh : g_Vh;
            bf16* Dl = (z == 0) ? g_Ql : (z == 1) ? g_Kl : g_Vl;
            #pragma unroll
            for (int i = 0; i < 4; i++)
                #pragma unroll
                for (int h = 0; h < 2; h++) {
                    const int m = m0 + wm0 + i * 16 + (lane >> 2) + 8 * h;
                    #pragma unroll
                    for (int j = 0; j < 4; j++) {
                        const int col = n0 + wn0 + j * 8 + 2 * (lane & 3);
                        const float2 bs = *(const float2*)(bias + col);
                        const float v0 = c[i][j][2 * h] + bs.x;
                        const float v1 = c[i][j][2 * h + 1] + bs.y;
                        bf16 h0, h1, l0, l1;
                        split_val(v0, h0, l0);
                        split_val(v1, h1, l1);
                        const size_t idx = (size_t)m * DDIM + col;
                        *(uint32_t*)(Dh + idx) = pack_bf16(h0, h1);
                        *(uint32_t*)(Dl + idx) = pack_bf16(l0, l1);
                    }
                }
            ZERO_ACC(c);
        }
        st = (st == 2) ? 0 : st + 1;
    }
}

// ---------------------------------------------------------------------------
// Kernel 2: scores + mask*exp + split store W + fused rowsum atomics.
// Persistent CTAs, continuous ring.
// ---------------------------------------------------------------------------
__global__ __launch_bounds__(256, 1)
void score_mma_kernel(const float* __restrict__ adj)
{
    extern __shared__ char smem[];
    const uint32_t sb = smem_to_u32(smem);
    const int tid = threadIdx.x, wid = tid >> 5, lane = tid & 31;
    const int wm0 = (wid & 1) * 64, wn0 = (wid >> 1) * 32;
    const int bid = blockIdx.x, grid = gridDim.x;
    const int NT = 2048;
    const int total = ((NT - 1 - bid) / grid + 1) * 8;

    score_issue(0, bid, grid, tid, sb);
    cp_commit();
    if (total > 1) score_issue(1, bid, grid, tid, sb + STAGE);
    cp_commit();

    float c[4][4][4];
    ZERO_ACC(c);
    int st = 0;
    for (int gc = 0; gc < total; gc++) {
        if (gc == total - 1) cp_wait0(); else cp_wait1();
        __syncthreads();
        compute_nt(sb + st * STAGE, c, lane, wm0, wn0);
        if (gc + 2 < total) {
            int st2 = st - 1; if (st2 < 0) st2 = 2;
            score_issue(gc + 2, bid, grid, tid, sb + st2 * STAGE);
        }
        cp_commit();
        if ((gc & 7) == 7) {
            const int t = bid + (gc >> 3) * grid;
            const int c0 = (t & 15) << 7;
            const int q0 = ((t >> 4) & 15) << 7;
            const int b = t >> 8;
            #pragma unroll
            for (int i = 0; i < 4; i++)
                #pragma unroll
                for (int h = 0; h < 2; h++) {
                    const int r = q0 + wm0 + i * 16 + (lane >> 2) + 8 * h;
                    const size_t rowbase = ((size_t)b * NN + r) * NN;
                    float rsum = 0.f;
                    #pragma unroll
                    for (int j = 0; j < 4; j++) {
                        const int cc = c0 + wn0 + j * 8 + 2 * (lane & 3);
                        const float2 a2 = *(const float2*)(adj + rowbase + cc);
                        const float w0 = a2.x * __expf(c[i][j][2 * h]);
                        const float w1 = a2.y * __expf(c[i][j][2 * h + 1]);
                        rsum += w0 + w1;
                        bf16 h0, h1, l0, l1;
                        split_val(w0, h0, l0);
                        split_val(w1, h1, l1);
                        *(uint32_t*)(g_Wmh + rowbase + cc) = pack_bf16(h0, h1);
                        *(uint32_t*)(g_Wml + rowbase + cc) = pack_bf16(l0, l1);
                    }
                    rsum += __shfl_xor_sync(0xffffffffu, rsum, 1);
                    rsum += __shfl_xor_sync(0xffffffffu, rsum, 2);
                    if ((lane & 3) == 0)
                        atomicAdd(&g_rs[b * NN + r], rsum);
                }
            ZERO_ACC(c);
        }
        st = (st == 2) ? 0 : st + 1;
    }
}

// ---------------------------------------------------------------------------
// Kernel 3: O = (W @ V) / rowsum.  Persistent CTAs, continuous ring. NIT=32.
// ---------------------------------------------------------------------------
__global__ __launch_bounds__(256, 1)
void out_mma_kernel(float* __restrict__ out)
{
    extern __shared__ char smem[];
    const uint32_t sb = smem_to_u32(smem);
    const int tid = threadIdx.x, wid = tid >> 5, lane = tid & 31;
    const int wm0 = (wid & 1) * 64, wn0 = (wid >> 1) * 32;
    const int bid = blockIdx.x, grid = gridDim.x;
    const int NT = 512;
    int ntm = (NT - 1 - bid) / grid + 1;
    if (bid >= NT) return;
    const int total = ntm * 32;

    out_issue(0, bid, grid, tid, sb);
    cp_commit();
    if (total > 1) out_issue(1, bid, grid, tid, sb + STAGE);
    cp_commit();

    float c[4][4][4];
    ZERO_ACC(c);
    int st = 0;
    for (int gc = 0; gc < total; gc++) {
        if (gc == total - 1) cp_wait0(); else cp_wait1();
        __syncthreads();
        compute_tr(sb + st * STAGE, c, lane, wm0, wn0);
        if (gc + 2 < total) {
            int st2 = st - 1; if (st2 < 0) st2 = 2;
            out_issue(gc + 2, bid, grid, tid, sb + st2 * STAGE);
        }
        cp_commit();
        if ((gc & 31) == 31) {
            const int t = bid + (gc >> 5) * grid;
            const int n0 = (t & 3) << 7;
            const int q0 = ((t >> 2) & 15) << 7;
            const int b = t >> 6;
            #pragma unroll
            for (int i = 0; i < 4; i++)
                #pragma unroll
                for (int h = 0; h < 2; h++) {
                    const int r = q0 + wm0 + i * 16 + (lane >> 2) + 8 * h;
                    const float inv = 1.0f / g_rs[b * NN + r];
                    float* op = out + ((size_t)b * NN + r) * DDIM;
                    #pragma unroll
                    for (int j = 0; j < 4; j++) {
                        const int col = n0 + wn0 + j * 8 + 2 * (lane & 3);
                        float2 v;
                        v.x = c[i][j][2 * h] * inv;
                        v.y = c[i][j][2 * h + 1] * inv;
                        *(float2*)(op + col) = v;
                    }
                }
            ZERO_ACC(c);
        }
        st = (st == 2) ? 0 : st + 1;
    }
}

// ---------------------------------------------------------------------------
// Prep: all fp32 -> (hi, lo) bf16 splits + rowsum zero, ONE launch.
// ---------------------------------------------------------------------------
static constexpr int NX4 = BB * NN * DDIM / 4;
static constexpr int NW4 = DDIM * DDIM / 4;
static constexpr int NPREP = NX4 + 3 * NW4;

__global__ void prep_kernel(const float* __restrict__ x,
                            const float* __restrict__ wq,
                            const float* __restrict__ wk,
                            const float* __restrict__ wv)
{
    const int i = blockIdx.x * blockDim.x + threadIdx.x;
    if (i < BB * NN) g_rs[i] = 0.f;
    if (i >= NPREP) return;

    const float* src;
    bf16 *h, *l;
    int j;
    if (i < NX4)               { src = x;  h = g_xh;  l = g_xl;  j = i; }
    else if (i < NX4 + NW4)    { src = wq; h = g_wqh; l = g_wql; j = i - NX4; }
    else if (i < NX4 + 2*NW4)  { src = wk; h = g_wkh; l = g_wkl; j = i - NX4 - NW4; }
    else                       { src = wv; h = g_wvh; l = g_wvl; j = i - NX4 - 2*NW4; }

    float4 v = ((const float4*)src)[j];
    bf16 h0, h1, h2, h3, l0, l1, l2, l3;
    split_val(v.x, h0, l0); split_val(v.y, h1, l1);
    split_val(v.z, h2, l2); split_val(v.w, h3, l3);
    ((uint2*)h)[j] = make_uint2(pack_bf16(h0, h1), pack_bf16(h2, h3));
    ((uint2*)l)[j] = make_uint2(pack_bf16(l0, l1), pack_bf16(l2, l3));
}

// ---------------------------------------------------------------------------
extern "C" void kernel_launch(void* const* d_in, const int* in_sizes, int n_in,
                              void* d_out, int out_size)
{
    const float* x    = (const float*)d_in[0];
    const float* adj  = (const float*)d_in[1];
    const float* Wq_w = (const float*)d_in[2];
    const float* Wq_b = (const float*)d_in[3];
    const float* Wk_w = (const float*)d_in[4];
    const float* Wk_b = (const float*)d_in[5];
    const float* Wv_w = (const float*)d_in[6];
    const float* Wv_b = (const float*)d_in[7];
    float* out = (float*)d_out;

    cudaFuncSetAttribute(qkv_mma_kernel, cudaFuncAttributeMaxDynamicSharedMemorySize, SMEM_TOTAL);
    cudaFuncSetAttribute(score_mma_kernel, cudaFuncAttributeMaxDynamicSharedMemorySize, SMEM_TOTAL);
    cudaFuncSetAttribute(out_mma_kernel, cudaFuncAttributeMaxDynamicSharedMemorySize, SMEM_TOTAL);

    int sms = 148;
    cudaDeviceGetAttribute(&sms, cudaDevAttrMultiProcessorCount, 0);

    prep_kernel<<<(NPREP + 255) / 256, 256>>>(x, Wq_w, Wk_w, Wv_w);
    qkv_mma_kernel<<<sms, 256, SMEM_TOTAL>>>(Wq_b, Wk_b, Wv_b);
    score_mma_kernel<<<sms, 256, SMEM_TOTAL>>>(adj);
    out_mma_kernel<<<sms, 256, SMEM_TOTAL>>>(out);
}